// round 16
// baseline (speedup 1.0000x reference)
#include <cuda_runtime.h>
#include <cuda_fp16.h>
#include <math.h>
#include <stdint.h>

#define NWIN 2048
#define NT   66
#define NH   8
#define QK_SCALE 0.17677669529663687f
#define NTHREADS 512

// ---- smem byte offsets ----
#define XHI_B 0u                 // 80 rows x 264 halves x 2B = 42240
#define XLO_B 42240u             // -> 84480
// 4 B-staging buffers, each hi 7680 + lo 7680 (96 rows x 40 halves, stride 80B)
#define BSTG_B 84480u            // buf k: hi = 84480 + k*15360, lo = hi + 7680 -> end 145920
// QA/KB overlay on buffers 2,3 (dead by the time epilogue writes them)
#define QA_HI 115200u            // 80 x 40 halves (stride 80B) = 6400
#define QA_LO 121600u
#define KB_HI 130560u            // 96 x 40 halves = 7680
#define KB_LO 138240u
#define SS_B  145920u            // fp32 scores 66 x 68 = 17952 -> 163872
#define VT_HI 163872u            // V^T 32 x 88 halves (stride 176B) = 5632
#define VT_LO 169504u            // -> 175136
#define PA_HI 175136u            // P 80 x 88 halves (stride 176B) = 14080
#define PA_LO 189216u            // -> 203296
#define SMEM_BYTES 203296u

// ---- preconverted hi/lo fp16 weights (uint2 = 4 halves) ----
__device__ uint2 WQH_g[768 * 64];
__device__ uint2 WQL_g[768 * 64];
__device__ uint2 WPH_g[256 * 64];
__device__ uint2 WPL_g[256 * 64];
// ---- O accumulator scratch: fp16 hi/lo, [2048][66][256] ----
__device__ __align__(16) unsigned short OHI_g[(size_t)NWIN * NT * 256];
__device__ __align__(16) unsigned short OLO_g[(size_t)NWIN * NT * 256];

static __device__ __forceinline__ uint32_t smem_u32(const void* p) {
    uint32_t a;
    asm("{ .reg .u64 t; cvta.to.shared.u64 t, %1; cvt.u32.u64 %0, t; }" : "=r"(a) : "l"(p));
    return a;
}

static __device__ __forceinline__ void ldsm4(uint32_t addr, uint32_t r[4]) {
    asm volatile("ldmatrix.sync.aligned.m8n8.x4.shared.b16 {%0,%1,%2,%3}, [%4];"
                 : "=r"(r[0]), "=r"(r[1]), "=r"(r[2]), "=r"(r[3]) : "r"(addr));
}
static __device__ __forceinline__ void mma16816(float d[4], const uint32_t a[4],
                                                uint32_t b0, uint32_t b1) {
    asm volatile("mma.sync.aligned.m16n8k16.row.col.f32.f16.f16.f32 "
                 "{%0,%1,%2,%3}, {%4,%5,%6,%7}, {%8,%9}, {%0,%1,%2,%3};"
                 : "+f"(d[0]), "+f"(d[1]), "+f"(d[2]), "+f"(d[3])
                 : "r"(a[0]), "r"(a[1]), "r"(a[2]), "r"(a[3]), "r"(b0), "r"(b1));
}
static __device__ __forceinline__ void mma_block(
    float acc[4][4], const uint32_t a[4], const uint32_t b0[4], const uint32_t b1[4])
{
    mma16816(acc[0], a, b0[0], b0[1]);
    mma16816(acc[1], a, b0[2], b0[3]);
    mma16816(acc[2], a, b1[0], b1[1]);
    mma16816(acc[3], a, b1[2], b1[3]);
}

static __device__ __forceinline__ uint32_t packh(__half a, __half b) {
    __half2 h = __halves2half2(a, b);
    return *reinterpret_cast<uint32_t*>(&h);
}
static __device__ __forceinline__ void hilo1(float v, __half& h, __half& l) {
    h = __float2half_rn(v);
    l = __float2half_rn(v - __half2float(h));
}
static __device__ __forceinline__ void cvt_hilo(float4 v, uint2& uh, uint2& ul) {
    __half a0, a1, a2, a3, b0, b1, b2, b3;
    hilo1(v.x, a0, b0); hilo1(v.y, a1, b1);
    hilo1(v.z, a2, b2); hilo1(v.w, a3, b3);
    uh.x = packh(a0, a1); uh.y = packh(a2, a3);
    ul.x = packh(b0, b1); ul.y = packh(b2, b3);
}

// ---- weight precompute: fp32 -> hi/lo fp16 arrays ----
__global__ void precvt_k(const float* __restrict__ qkv_w,
                         const float* __restrict__ proj_w) {
    int i = blockIdx.x * 256 + threadIdx.x;
    float4 v;
    uint2 uh, ul;
    if (i < 49152) {
        v = ((const float4*)qkv_w)[i];
        cvt_hilo(v, uh, ul);
        WQH_g[i] = uh; WQL_g[i] = ul;
    } else {
        int j = i - 49152;
        v = ((const float4*)proj_w)[j];
        cvt_hilo(v, uh, ul);
        WPH_g[j] = uh; WPL_g[j] = ul;
    }
}

// ---- stage TWO k32 chunks (chunks kc0, kc0+1): 1536 slots, 3 per thread ----
static __device__ __forceinline__ void b_ldg2(
    int mode, int h, int colbase, int nvalid, int kc0, int tid,
    uint2 sh[3], uint2 sl[3])
{
    const uint2* __restrict__ Wh = mode ? WPH_g : WQH_g;
    const uint2* __restrict__ Wl = mode ? WPL_g : WQL_g;
#pragma unroll
    for (int u = 0; u < 3; u++) {
        int idx = tid + u * 512;           // 0..1535
        int ch  = (idx >= 768) ? 1 : 0;
        int s   = idx - ch * 768;
        int n = s >> 3, f4 = s & 7;
        if (n < nvalid) {
            int grow = mode ? (colbase + n) : (((n >> 5) << 8) | (h << 5) | (n & 31));
            int q = grow * 64 + (kc0 + ch) * 8 + f4;
            sh[u] = Wh[q]; sl[u] = Wl[q];
        } else {
            sh[u] = make_uint2(0u, 0u); sl[u] = make_uint2(0u, 0u);
        }
    }
}
static __device__ __forceinline__ void b_sts2(
    char* smb, int kc0, int tid, const uint2 sh[3], const uint2 sl[3])
{
#pragma unroll
    for (int u = 0; u < 3; u++) {
        int idx = tid + u * 512;
        int ch  = (idx >= 768) ? 1 : 0;
        int s   = idx - ch * 768;
        int n = s >> 3, f4 = s & 7;
        uint32_t bh = BSTG_B + (uint32_t)(((kc0 + ch) & 3) * 15360);
        *(uint2*)(smb + bh + n * 80 + f4 * 8)        = sh[u];
        *(uint2*)(smb + bh + 7680 + n * 80 + f4 * 8) = sl[u];
    }
}

// ---- one k32 chunk of MMAs for warp tile m16 x n32 (3-pass hi/lo split) ----
static __device__ __forceinline__ void mma_chunk(
    uint32_t smu, int buf, int kbase_h, int wm, int wn, int lane, float acc[4][4])
{
    uint32_t bh = BSTG_B + (uint32_t)(buf * 15360);
    uint32_t bl = bh + 7680u;
    uint32_t rowA = (uint32_t)(wm * 16 + (lane & 15));
    uint32_t aoff = rowA * 528u + (uint32_t)((lane >> 4) * 16);
    uint32_t nloc = (uint32_t)(((lane >> 4) << 3) + (lane & 7));
    uint32_t boff = (uint32_t)(wn * 32 + nloc) * 80u + (uint32_t)(((lane >> 3) & 1) * 16);
#pragma unroll
    for (int s = 0; s < 2; s++) {
        uint32_t kg = (uint32_t)(kbase_h + s * 16);
        uint32_t ah[4], al[4], bh0[4], bh1[4], bl0[4], bl1[4];
        ldsm4(smu + XHI_B + aoff + kg * 2, ah);
        ldsm4(smu + XLO_B + aoff + kg * 2, al);
        uint32_t bk = (uint32_t)(s * 32);
        ldsm4(smu + bh + boff + bk, bh0);
        ldsm4(smu + bh + boff + 1280 + bk, bh1);
        ldsm4(smu + bl + boff + bk, bl0);
        ldsm4(smu + bl + boff + 1280 + bk, bl1);
        mma_block(acc, ah, bh0, bh1);
        mma_block(acc, ah, bl0, bl1);
        mma_block(acc, al, bh0, bh1);
    }
}

// ---- full K=256 GEMM: 4 iterations of k64, chunks 0,1 pre-staged ----
// At i==3, stages chunks 0,1 of the NEXT gemm (if has_next).
static __device__ __forceinline__ void gemm_full(
    int mode, int h, int colbase, int nvalid,
    int nmode, int nh, int ncolbase, int nnvalid, bool has_next, bool wactive,
    char* smb, uint32_t smu, int tid, int warp, int lane, float acc[4][4])
{
    const int wm = warp / 3, wn = warp % 3;
    uint2 sh[3], sl[3];
#pragma unroll 1
    for (int i = 0; i < 4; i++) {
        bool do_stage = (i < 3) || has_next;
        if (do_stage) {
            if (i < 3) b_ldg2(mode, h, colbase, nvalid, 2 * i + 2, tid, sh, sl);
            else       b_ldg2(nmode, nh, ncolbase, nnvalid, 0, tid, sh, sl);
        }
        if (warp < 15 && wactive) {
            mma_chunk(smu, (2 * i) & 3,     2 * i * 32,       wm, wn, lane, acc);
            mma_chunk(smu, (2 * i + 1) & 3, (2 * i + 1) * 32, wm, wn, lane, acc);
        }
        if (do_stage) b_sts2(smb, (i < 3) ? (2 * i + 2) : 0, tid, sh, sl);
        __syncthreads();
    }
}

__global__ __launch_bounds__(NTHREADS, 1)
void winattn_mma(const float* __restrict__ x,
                 const float* __restrict__ qkv_b,
                 const float* __restrict__ rbt,
                 const float* __restrict__ proj_b,
                 float* __restrict__ out)
{
    extern __shared__ char smb[];
    const uint32_t smu = smem_u32(smb);
    float* SSf = (float*)(smb + SS_B);

    const int tid  = threadIdx.x;
    const int warp = tid >> 5;
    const int lane = tid & 31;
    const int wm = warp / 3, wn = warp % 3;
    const int b = blockIdx.x;
    const float* xg = x + (size_t)b * NT * 256;
    float* og = out + (size_t)b * NT * 256;

    // ---- init: X -> fp16 hi/lo smem, zero pads, zero VT/PA, stage chunks 0,1 ----
    for (int idx = tid; idx < NT * 64; idx += NTHREADS) {
        int n = idx >> 6, c4 = (idx & 63) << 2;
        float4 v = *(const float4*)(xg + n * 256 + c4);
        uint2 uh, ul;
        cvt_hilo(v, uh, ul);
        *(uint2*)(smb + XHI_B + n * 528 + c4 * 2) = uh;
        *(uint2*)(smb + XLO_B + n * 528 + c4 * 2) = ul;
    }
    {
        uint4 z = make_uint4(0u, 0u, 0u, 0u);
        for (int idx = tid; idx < 14 * 33; idx += NTHREADS) {
            int r = 66 + idx / 33, q = idx % 33;
            *(uint4*)(smb + XHI_B + r * 528 + q * 16) = z;
            *(uint4*)(smb + XLO_B + r * 528 + q * 16) = z;
        }
        // zero VT + PA (163872..203296 = 39424 B)
        for (int idx = tid; idx < 2464; idx += NTHREADS)
            *(uint4*)(smb + VT_HI + idx * 16) = z;
    }
    {
        uint2 sh[3], sl[3];
        b_ldg2(0, 0, 0, 96, 0, tid, sh, sl);
        b_sts2(smb, 0, tid, sh, sl);
    }
    __syncthreads();

    const int c1 = lane + 32;
    const bool has2 = (lane < 2);
    const int c2 = lane + 64;

    for (int h = 0; h < NH; h++) {
        float acc[4][4];
#pragma unroll
        for (int j = 0; j < 4; j++)
#pragma unroll
            for (int q = 0; q < 4; q++) acc[j][q] = 0.f;

        // next gemm: head h+1, or proj t=0 after last head
        int nmode = (h < 7) ? 0 : 1;
        int nh    = (h < 7) ? (h + 1) : 0;
        gemm_full(0, h, 0, 96, nmode, nh, 0, 96, true, true,
                  smb, smu, tid, warp, lane, acc);

        // ---- QKV epilogue: fragments -> QA/KB (B2/B3 overlay) + VT ----
        if (warp < 15) {
            int r0 = wm * 16 + (lane >> 2), r1 = r0 + 8;
#pragma unroll
            for (int j = 0; j < 4; j++) {
                int col = wn * 32 + j * 8 + ((lane & 3) << 1);
                int m = col >> 5, d = col & 31;
                float bb0 = qkv_b[(m << 8) + (h << 5) + d];
                float bb1 = qkv_b[(m << 8) + (h << 5) + d + 1];
                float x0 = acc[j][0] + bb0, x1 = acc[j][1] + bb1;
                float x2 = acc[j][2] + bb0, x3 = acc[j][3] + bb1;
                if (m == 0) { x0 *= QK_SCALE; x1 *= QK_SCALE; x2 *= QK_SCALE; x3 *= QK_SCALE; }
                __half h0, l0, h1, l1, h2, l2, h3, l3;
                hilo1(x0, h0, l0); hilo1(x1, h1, l1);
                hilo1(x2, h2, l2); hilo1(x3, h3, l3);
                if (m < 2) {
                    uint32_t bhb = (m == 0) ? QA_HI : KB_HI;
                    uint32_t blb = (m == 0) ? QA_LO : KB_LO;
                    if (r0 < NT) {
                        *(uint32_t*)(smb + bhb + r0 * 80 + d * 2) = packh(h0, h1);
                        *(uint32_t*)(smb + blb + r0 * 80 + d * 2) = packh(l0, l1);
                    }
                    if (r1 < NT) {
                        *(uint32_t*)(smb + bhb + r1 * 80 + d * 2) = packh(h2, h3);
                        *(uint32_t*)(smb + blb + r1 * 80 + d * 2) = packh(l2, l3);
                    }
                } else {  // v transposed: VT[d][token]
                    if (r0 < NT) {
                        *(__half*)(smb + VT_HI + d * 176 + r0 * 2)       = h0;
                        *(__half*)(smb + VT_HI + (d + 1) * 176 + r0 * 2) = h1;
                        *(__half*)(smb + VT_LO + d * 176 + r0 * 2)       = l0;
                        *(__half*)(smb + VT_LO + (d + 1) * 176 + r0 * 2) = l1;
                    }
                    if (r1 < NT) {
                        *(__half*)(smb + VT_HI + d * 176 + r1 * 2)       = h2;
                        *(__half*)(smb + VT_HI + (d + 1) * 176 + r1 * 2) = h3;
                        *(__half*)(smb + VT_LO + d * 176 + r1 * 2)       = l2;
                        *(__half*)(smb + VT_LO + (d + 1) * 176 + r1 * 2) = l3;
                    }
                }
            }
        }
        __syncthreads();

        // ---- scores MMA + bias -> SS (dedicated; single phase) ----
        if (warp < 15) {
            float sacc[4][4];
#pragma unroll
            for (int j = 0; j < 4; j++)
#pragma unroll
                for (int q = 0; q < 4; q++) sacc[j][q] = 0.f;
            uint32_t aoffq = (uint32_t)((wm * 16 + (lane & 15)) * 80 + ((lane >> 4) << 4));
            uint32_t nloc = (uint32_t)(((lane >> 4) << 3) + (lane & 7));
            uint32_t boffk = (uint32_t)((wn * 32 + nloc) * 80 + (((lane >> 3) & 1) << 4));
#pragma unroll
            for (int s = 0; s < 2; s++) {
                uint32_t ko = (uint32_t)(s * 32);
                uint32_t qh[4], ql[4], kh0[4], kh1[4], kl0[4], kl1[4];
                ldsm4(smu + QA_HI + aoffq + ko, qh);
                ldsm4(smu + QA_LO + aoffq + ko, ql);
                ldsm4(smu + KB_HI + boffk + ko, kh0);
                ldsm4(smu + KB_LO + boffk + ko, kl0);
                mma16816(sacc[0], qh, kh0[0], kh0[1]);
                mma16816(sacc[1], qh, kh0[2], kh0[3]);
                mma16816(sacc[0], qh, kl0[0], kl0[1]);
                mma16816(sacc[1], qh, kl0[2], kl0[3]);
                mma16816(sacc[0], ql, kh0[0], kh0[1]);
                mma16816(sacc[1], ql, kh0[2], kh0[3]);
                if (wn < 2) {
                    ldsm4(smu + KB_HI + boffk + 1280u + ko, kh1);
                    ldsm4(smu + KB_LO + boffk + 1280u + ko, kl1);
                    mma16816(sacc[2], qh, kh1[0], kh1[1]);
                    mma16816(sacc[3], qh, kh1[2], kh1[3]);
                    mma16816(sacc[2], qh, kl1[0], kl1[1]);
                    mma16816(sacc[3], qh, kl1[2], kl1[3]);
                    mma16816(sacc[2], ql, kh1[0], kh1[1]);
                    mma16816(sacc[3], ql, kh1[2], kh1[3]);
                }
            }
            int r0 = wm * 16 + (lane >> 2);
#pragma unroll
            for (int j = 0; j < 4; j++) {
                int col = wn * 32 + j * 8 + ((lane & 3) << 1);
#pragma unroll
                for (int e = 0; e < 4; e++) {
                    int r = (e < 2) ? r0 : r0 + 8;
                    int c = col + (e & 1);
                    if (r < NT && c < NT) {
                        float s = sacc[j][e];
                        if (r >= 2 && c >= 2) {
                            int i2 = r - 2, j2 = c - 2;
                            int bi = (((i2 >> 3) - (j2 >> 3) + 7) * 15)
                                   + ((i2 & 7) - (j2 & 7) + 7);
                            s += rbt[bi * NH + h];
                        }
                        SSf[r * 68 + c] = s;
                    }
                }
            }
        }
        __syncthreads();

        // ---- softmax: SS -> P fp16 hi/lo fragments ----
        for (int row = warp; row < NT; row += 16) {
            float* sp = &SSf[row * 68];
            float v0 = sp[lane], v1 = sp[c1];
            float v2 = has2 ? sp[c2] : -INFINITY;
            float mx = fmaxf(fmaxf(v0, v1), v2);
#pragma unroll
            for (int o = 16; o > 0; o >>= 1)
                mx = fmaxf(mx, __shfl_xor_sync(0xffffffffu, mx, o));
            float e0 = __expf(v0 - mx), e1 = __expf(v1 - mx);
            float e2 = has2 ? __expf(v2 - mx) : 0.f;
            float s = e0 + e1 + e2;
#pragma unroll
            for (int o = 16; o > 0; o >>= 1)
                s += __shfl_xor_sync(0xffffffffu, s, o);
            float inv = 1.f / s;
            __half ph, pl;
            hilo1(e0 * inv, ph, pl);
            *(__half*)(smb + PA_HI + row * 176 + lane * 2) = ph;
            *(__half*)(smb + PA_LO + row * 176 + lane * 2) = pl;
            hilo1(e1 * inv, ph, pl);
            *(__half*)(smb + PA_HI + row * 176 + c1 * 2) = ph;
            *(__half*)(smb + PA_LO + row * 176 + c1 * 2) = pl;
            if (has2) {
                hilo1(e2 * inv, ph, pl);
                *(__half*)(smb + PA_HI + row * 176 + c2 * 2) = ph;
                *(__half*)(smb + PA_LO + row * 176 + c2 * 2) = pl;
            }
        }
        __syncthreads();

        // ---- PV MMA (warps 0-9, m16n16): O -> global fp16 hi/lo ----
        // NO barrier after: warps 10-15 flow into next gemm i=0 (disjoint smem).
        if (warp < 10) {
            float pacc[2][4];
#pragma unroll
            for (int j = 0; j < 2; j++)
#pragma unroll
                for (int q = 0; q < 4; q++) pacc[j][q] = 0.f;
            int pwm = warp >> 1, pwn = warp & 1;
            uint32_t aoffp = (uint32_t)((pwm * 16 + (lane & 15)) * 176 + ((lane >> 4) << 4));
            uint32_t nloc = (uint32_t)(((lane >> 4) << 3) + (lane & 7));
            uint32_t boffv = (uint32_t)((pwn * 16 + nloc) * 176 + (((lane >> 3) & 1) << 4));
#pragma unroll
            for (int s = 0; s < 5; s++) {
                uint32_t ko = (uint32_t)(s * 32);
                uint32_t ph4[4], pl4[4], vh[4], vl[4];
                ldsm4(smu + PA_HI + aoffp + ko, ph4);
                ldsm4(smu + PA_LO + aoffp + ko, pl4);
                ldsm4(smu + VT_HI + boffv + ko, vh);
                ldsm4(smu + VT_LO + boffv + ko, vl);
                mma16816(pacc[0], ph4, vh[0], vh[1]);
                mma16816(pacc[1], ph4, vh[2], vh[3]);
                mma16816(pacc[0], ph4, vl[0], vl[1]);
                mma16816(pacc[1], ph4, vl[2], vl[3]);
                mma16816(pacc[0], pl4, vh[0], vh[1]);
                mma16816(pacc[1], pl4, vh[2], vh[3]);
            }
            int r0 = pwm * 16 + (lane >> 2), r1 = r0 + 8;
#pragma unroll
            for (int j = 0; j < 2; j++) {
                int c = (h << 5) + pwn * 16 + j * 8 + ((lane & 3) << 1);
                __half h0, l0, h1, l1;
                if (r0 < NT) {
                    hilo1(pacc[j][0], h0, l0); hilo1(pacc[j][1], h1, l1);
                    size_t gi = ((size_t)b * NT + r0) * 256 + c;
                    *(uint32_t*)&OHI_g[gi] = packh(h0, h1);
                    *(uint32_t*)&OLO_g[gi] = packh(l0, l1);
                }
                if (r1 < NT) {
                    hilo1(pacc[j][2], h0, l0); hilo1(pacc[j][3], h1, l1);
                    size_t gi = ((size_t)b * NT + r1) * 256 + c;
                    *(uint32_t*)&OHI_g[gi] = packh(h0, h1);
                    *(uint32_t*)&OLO_g[gi] = packh(l0, l1);
                }
            }
        }
        // intentionally no __syncthreads here
    }

    // ---- copy O back into XHI/XLO (X is dead) as proj A-operand ----
    __syncthreads();   // O global writes visible to all threads in block
    for (int idx = tid; idx < NT * 32; idx += NTHREADS) {
        int r = idx >> 5, q = idx & 31;   // uint4 = 8 halves
        size_t gi = (((size_t)b * NT + r) * 256 + q * 8);
        uint4 vh = *(const uint4*)&OHI_g[gi];
        uint4 vl = *(const uint4*)&OLO_g[gi];
        *(uint4*)(smb + XHI_B + r * 528 + q * 16) = vh;
        *(uint4*)(smb + XLO_B + r * 528 + q * 16) = vl;
    }
    __syncthreads();

    // ---- output projection: N=256 in 3 chunks of 96 (last 64 valid) ----
    // proj t=0 chunks 0,1 staged during h=7's gemm i=3
#pragma unroll 1
    for (int t = 0; t < 3; t++) {
        int nvalid = (t == 2) ? 64 : 96;
        bool wact = !(t == 2 && wn == 2);
        float acc[4][4];
#pragma unroll
        for (int j = 0; j < 4; j++)
#pragma unroll
            for (int q = 0; q < 4; q++) acc[j][q] = 0.f;

        gemm_full(1, 0, 96 * t, nvalid,
                  1, 0, 96 * (t + 1), (t == 1) ? 64 : 96, /*has_next=*/(t < 2), wact,
                  smb, smu, tid, warp, lane, acc);

        if (warp < 15 && wact) {
            int r0 = wm * 16 + (lane >> 2), r1 = r0 + 8;
#pragma unroll
            for (int j = 0; j < 4; j++) {
                int col = 96 * t + wn * 32 + j * 8 + ((lane & 3) << 1);
                if (col < 256) {
                    float pb0 = proj_b[col], pb1 = proj_b[col + 1];
                    if (r0 < NT) {
                        float2 v; v.x = acc[j][0] + pb0; v.y = acc[j][1] + pb1;
                        *(float2*)(og + r0 * 256 + col) = v;
                    }
                    if (r1 < NT) {
                        float2 v; v.x = acc[j][2] + pb0; v.y = acc[j][3] + pb1;
                        *(float2*)(og + r1 * 256 + col) = v;
                    }
                }
            }
        }
    }
}

extern "C" void kernel_launch(void* const* d_in, const int* in_sizes, int n_in,
                              void* d_out, int out_size) {
    const float* x      = (const float*)d_in[0];
    const float* qkv_w  = (const float*)d_in[1];
    const float* qkv_b  = (const float*)d_in[2];
    const float* rbt    = (const float*)d_in[3];
    const float* proj_w = (const float*)d_in[4];
    const float* proj_b = (const float*)d_in[5];
    float* out = (float*)d_out;

    precvt_k<<<256, 256>>>(qkv_w, proj_w);

    cudaFuncSetAttribute(winattn_mma,
                         cudaFuncAttributeMaxDynamicSharedMemorySize, SMEM_BYTES);
    winattn_mma<<<NWIN, NTHREADS, SMEM_BYTES>>>(x, qkv_b, rbt, proj_b, out);
}

// round 17
// speedup vs baseline: 1.5503x; 1.5503x over previous
#include <cuda_runtime.h>
#include <cuda_fp16.h>
#include <math.h>
#include <stdint.h>

#define NWIN 2048
#define NT   66
#define NH   8
#define QK_SCALE 0.17677669529663687f
#define NTHREADS 512

// ---- smem byte offsets (total 113,696 -> 2 CTAs/SM) ----
#define AST_B 0u          // A chunk bufs: +buf*12800; hi +0 (80x80B), lo +6400
#define BST_B 25600u      // B chunk bufs: +buf*15360; hi +0 (96x80B), lo +7680
#define QA_HI 56320u      // 80 x 80B
#define QA_LO 62720u
#define KB_HI 69120u      // 96 x 80B
#define KB_LO 76800u
#define PA_HI 56320u      // overlay of QA+KB: 80 x 176B
#define PA_LO 70400u
#define VT_HI 84480u      // 32 x 176B
#define VT_LO 90112u
#define SS_B  95744u      // fp32 66 x 68 = 17952 -> 113696
#define SMEM_BYTES 113696u

// ---- preconverted hi/lo fp16 weights (uint2 = 4 halves) ----
__device__ uint2 WQH_g[768 * 64];
__device__ uint2 WQL_g[768 * 64];
__device__ uint2 WPH_g[256 * 64];
__device__ uint2 WPL_g[256 * 64];
// ---- O accumulator scratch: fp16 hi/lo, [2048][66][256] ----
__device__ __align__(16) unsigned short OHI_g[(size_t)NWIN * NT * 256];
__device__ __align__(16) unsigned short OLO_g[(size_t)NWIN * NT * 256];

static __device__ __forceinline__ uint32_t smem_u32(const void* p) {
    uint32_t a;
    asm("{ .reg .u64 t; cvta.to.shared.u64 t, %1; cvt.u32.u64 %0, t; }" : "=r"(a) : "l"(p));
    return a;
}
static __device__ __forceinline__ void ldsm4(uint32_t addr, uint32_t r[4]) {
    asm volatile("ldmatrix.sync.aligned.m8n8.x4.shared.b16 {%0,%1,%2,%3}, [%4];"
                 : "=r"(r[0]), "=r"(r[1]), "=r"(r[2]), "=r"(r[3]) : "r"(addr));
}
static __device__ __forceinline__ void mma16816(float d[4], const uint32_t a[4],
                                                uint32_t b0, uint32_t b1) {
    asm volatile("mma.sync.aligned.m16n8k16.row.col.f32.f16.f16.f32 "
                 "{%0,%1,%2,%3}, {%4,%5,%6,%7}, {%8,%9}, {%0,%1,%2,%3};"
                 : "+f"(d[0]), "+f"(d[1]), "+f"(d[2]), "+f"(d[3])
                 : "r"(a[0]), "r"(a[1]), "r"(a[2]), "r"(a[3]), "r"(b0), "r"(b1));
}
static __device__ __forceinline__ void mma_block(
    float acc[4][4], const uint32_t a[4], const uint32_t b0[4], const uint32_t b1[4])
{
    mma16816(acc[0], a, b0[0], b0[1]);
    mma16816(acc[1], a, b0[2], b0[3]);
    mma16816(acc[2], a, b1[0], b1[1]);
    mma16816(acc[3], a, b1[2], b1[3]);
}
static __device__ __forceinline__ uint32_t packh(__half a, __half b) {
    __half2 h = __halves2half2(a, b);
    return *reinterpret_cast<uint32_t*>(&h);
}
static __device__ __forceinline__ void hilo1(float v, __half& h, __half& l) {
    h = __float2half_rn(v);
    l = __float2half_rn(v - __half2float(h));
}
static __device__ __forceinline__ void cvt_hilo(float4 v, uint2& uh, uint2& ul) {
    __half a0, a1, a2, a3, b0, b1, b2, b3;
    hilo1(v.x, a0, b0); hilo1(v.y, a1, b1);
    hilo1(v.z, a2, b2); hilo1(v.w, a3, b3);
    uh.x = packh(a0, a1); uh.y = packh(a2, a3);
    ul.x = packh(b0, b1); ul.y = packh(b2, b3);
}

// ---- weight precompute: fp32 -> hi/lo fp16 arrays ----
__global__ void precvt_k(const float* __restrict__ qkv_w,
                         const float* __restrict__ proj_w) {
    int i = blockIdx.x * 256 + threadIdx.x;
    float4 v; uint2 uh, ul;
    if (i < 49152) {
        v = ((const float4*)qkv_w)[i];
        cvt_hilo(v, uh, ul);
        WQH_g[i] = uh; WQL_g[i] = ul;
    } else {
        int j = i - 49152;
        v = ((const float4*)proj_w)[j];
        cvt_hilo(v, uh, ul);
        WPH_g[j] = uh; WPL_g[j] = ul;
    }
}

// ---- A-chunk staging: 640 slots (80 rows x 8 quads), rows>=66 zeroed ----
static __device__ __forceinline__ void a_ldg(
    int asrc, const float* __restrict__ xg, int b, int kc, int tid,
    uint2 ah[2], uint2 al[2])
{
#pragma unroll
    for (int u = 0; u < 2; u++) {
        int idx = tid + u * 512;
        if (idx < 640) {
            int n = idx >> 3, f4 = idx & 7;
            if (n < NT) {
                if (asrc == 0) {
                    float4 v = *(const float4*)(xg + n * 256 + kc * 32 + f4 * 4);
                    cvt_hilo(v, ah[u], al[u]);
                } else {
                    size_t off = ((size_t)b * NT + n) * 256 + kc * 32 + f4 * 4;
                    ah[u] = *(const uint2*)&OHI_g[off];
                    al[u] = *(const uint2*)&OLO_g[off];
                }
            } else {
                ah[u] = make_uint2(0u, 0u); al[u] = make_uint2(0u, 0u);
            }
        }
    }
}
static __device__ __forceinline__ void a_sts(
    char* smb, int buf, int tid, const uint2 ah[2], const uint2 al[2])
{
    uint32_t base = AST_B + (uint32_t)buf * 12800u;
#pragma unroll
    for (int u = 0; u < 2; u++) {
        int idx = tid + u * 512;
        if (idx < 640) {
            int n = idx >> 3, f4 = idx & 7;
            *(uint2*)(smb + base + n * 80 + f4 * 8)        = ah[u];
            *(uint2*)(smb + base + 6400 + n * 80 + f4 * 8) = al[u];
        }
    }
}

// ---- B-chunk staging (copy of preconverted weights): 768 slots ----
static __device__ __forceinline__ void b_ldg(
    int mode, int h, int colbase, int nvalid, int kc, int tid,
    uint2 sh[2], uint2 sl[2])
{
    const uint2* __restrict__ Wh = mode ? WPH_g : WQH_g;
    const uint2* __restrict__ Wl = mode ? WPL_g : WQL_g;
#pragma unroll
    for (int u = 0; u < 2; u++) {
        int idx = tid + u * 512;
        if (idx < 768) {
            int n = idx >> 3, f4 = idx & 7;
            if (n < nvalid) {
                int grow = mode ? (colbase + n) : (((n >> 5) << 8) | (h << 5) | (n & 31));
                int q = grow * 64 + kc * 8 + f4;
                sh[u] = Wh[q]; sl[u] = Wl[q];
            } else {
                sh[u] = make_uint2(0u, 0u); sl[u] = make_uint2(0u, 0u);
            }
        }
    }
}
static __device__ __forceinline__ void b_sts(
    char* smb, int buf, int tid, const uint2 sh[2], const uint2 sl[2])
{
    uint32_t base = BST_B + (uint32_t)buf * 15360u;
#pragma unroll
    for (int u = 0; u < 2; u++) {
        int idx = tid + u * 512;
        if (idx < 768) {
            int n = idx >> 3, f4 = idx & 7;
            *(uint2*)(smb + base + n * 80 + f4 * 8)        = sh[u];
            *(uint2*)(smb + base + 7680 + n * 80 + f4 * 8) = sl[u];
        }
    }
}

// ---- one k32 chunk of MMAs for warp tile m16 x n32 (3-pass hi/lo split) ----
static __device__ __forceinline__ void mma_chunk(
    uint32_t smu, int buf, int wm, int wn, int lane, float acc[4][4])
{
    uint32_t ab = AST_B + (uint32_t)buf * 12800u;
    uint32_t bb = BST_B + (uint32_t)buf * 15360u;
    uint32_t aoff = (uint32_t)((wm * 16 + (lane & 15)) * 80 + ((lane >> 4) << 4));
    uint32_t nloc = (uint32_t)(((lane >> 4) << 3) + (lane & 7));
    uint32_t boff = (uint32_t)(wn * 32 + nloc) * 80u + (uint32_t)(((lane >> 3) & 1) << 4);
#pragma unroll
    for (int s = 0; s < 2; s++) {
        uint32_t sk = (uint32_t)(s * 32);
        uint32_t ah[4], al[4], bh0[4], bh1[4], bl0[4], bl1[4];
        ldsm4(smu + ab + aoff + sk, ah);
        ldsm4(smu + ab + 6400u + aoff + sk, al);
        ldsm4(smu + bb + boff + sk, bh0);
        ldsm4(smu + bb + boff + 1280u + sk, bh1);
        ldsm4(smu + bb + 7680u + boff + sk, bl0);
        ldsm4(smu + bb + 7680u + boff + 1280u + sk, bl1);
        mma_block(acc, ah, bh0, bh1);
        mma_block(acc, ah, bl0, bl1);
        mma_block(acc, al, bh0, bh1);
    }
}

// ---- full K=256 GEMM with A+B double-buffered chunk staging ----
static __device__ __forceinline__ void gemm_full(
    int asrc, const float* __restrict__ xg, int b,
    int mode, int h, int colbase, int nvalid,
    char* smb, uint32_t smu, int tid, int warp, int lane, float acc[4][4])
{
    const int wm = warp / 3, wn = warp % 3;
    uint2 ah[2], al[2], sh[2], sl[2];
    a_ldg(asrc, xg, b, 0, tid, ah, al);
    b_ldg(mode, h, colbase, nvalid, 0, tid, sh, sl);
    a_sts(smb, 0, tid, ah, al);
    b_sts(smb, 0, tid, sh, sl);
    __syncthreads();
#pragma unroll 1
    for (int c = 0; c < 8; c++) {
        if (c < 7) {
            a_ldg(asrc, xg, b, c + 1, tid, ah, al);
            b_ldg(mode, h, colbase, nvalid, c + 1, tid, sh, sl);
        }
        if (warp < 15) mma_chunk(smu, c & 1, wm, wn, lane, acc);
        if (c < 7) {
            a_sts(smb, (c + 1) & 1, tid, ah, al);
            b_sts(smb, (c + 1) & 1, tid, sh, sl);
        }
        __syncthreads();
    }
}

__global__ __launch_bounds__(NTHREADS, 2)
void winattn_mma(const float* __restrict__ x,
                 const float* __restrict__ qkv_b,
                 const float* __restrict__ rbt,
                 const float* __restrict__ proj_b,
                 float* __restrict__ out)
{
    extern __shared__ char smb[];
    const uint32_t smu = smem_u32(smb);
    float* SSf = (float*)(smb + SS_B);

    const int tid  = threadIdx.x;
    const int warp = tid >> 5;
    const int lane = tid & 31;
    const int wm = warp / 3, wn = warp % 3;
    const int b = blockIdx.x;
    const float* xg = x + (size_t)b * NT * 256;
    float* og = out + (size_t)b * NT * 256;

    // zero VT hi+lo (84480..95744 = 704 uint4); pad cols must stay zero
    {
        uint4 z = make_uint4(0u, 0u, 0u, 0u);
        for (int idx = tid; idx < 704; idx += NTHREADS)
            *(uint4*)(smb + VT_HI + idx * 16) = z;
    }
    // ordered before first epilogue by gemm_full's internal barriers

    const int c1 = lane + 32;
    const bool has2 = (lane < 2);
    const int c2 = lane + 64;

    for (int h = 0; h < NH; h++) {
        float acc[4][4];
#pragma unroll
        for (int j = 0; j < 4; j++)
#pragma unroll
            for (int q = 0; q < 4; q++) acc[j][q] = 0.f;

        gemm_full(0, xg, b, 0, h, 0, 96, smb, smu, tid, warp, lane, acc);

        // ---- QKV epilogue: fragments -> QA/KB + VT (fp16 hi/lo) ----
        if (warp < 15) {
            int r0 = wm * 16 + (lane >> 2), r1 = r0 + 8;
#pragma unroll
            for (int j = 0; j < 4; j++) {
                int col = wn * 32 + j * 8 + ((lane & 3) << 1);
                int m = col >> 5, d = col & 31;
                float bb0 = qkv_b[(m << 8) + (h << 5) + d];
                float bb1 = qkv_b[(m << 8) + (h << 5) + d + 1];
                float x0 = acc[j][0] + bb0, x1 = acc[j][1] + bb1;
                float x2 = acc[j][2] + bb0, x3 = acc[j][3] + bb1;
                if (m == 0) { x0 *= QK_SCALE; x1 *= QK_SCALE; x2 *= QK_SCALE; x3 *= QK_SCALE; }
                __half h0, l0, h1, l1, h2, l2, h3, l3;
                hilo1(x0, h0, l0); hilo1(x1, h1, l1);
                hilo1(x2, h2, l2); hilo1(x3, h3, l3);
                if (m < 2) {
                    uint32_t bhb = (m == 0) ? QA_HI : KB_HI;
                    uint32_t blb = (m == 0) ? QA_LO : KB_LO;
                    if (r0 < NT) {
                        *(uint32_t*)(smb + bhb + r0 * 80 + d * 2) = packh(h0, h1);
                        *(uint32_t*)(smb + blb + r0 * 80 + d * 2) = packh(l0, l1);
                    }
                    if (r1 < NT) {
                        *(uint32_t*)(smb + bhb + r1 * 80 + d * 2) = packh(h2, h3);
                        *(uint32_t*)(smb + blb + r1 * 80 + d * 2) = packh(l2, l3);
                    }
                } else {
                    if (r0 < NT) {
                        *(__half*)(smb + VT_HI + d * 176 + r0 * 2)       = h0;
                        *(__half*)(smb + VT_HI + (d + 1) * 176 + r0 * 2) = h1;
                        *(__half*)(smb + VT_LO + d * 176 + r0 * 2)       = l0;
                        *(__half*)(smb + VT_LO + (d + 1) * 176 + r0 * 2) = l1;
                    }
                    if (r1 < NT) {
                        *(__half*)(smb + VT_HI + d * 176 + r1 * 2)       = h2;
                        *(__half*)(smb + VT_HI + (d + 1) * 176 + r1 * 2) = h3;
                        *(__half*)(smb + VT_LO + d * 176 + r1 * 2)       = l2;
                        *(__half*)(smb + VT_LO + (d + 1) * 176 + r1 * 2) = l3;
                    }
                }
            }
        }
        __syncthreads();

        // ---- scores MMA + rel-pos bias -> SS ----
        if (warp < 15) {
            float sacc[4][4];
#pragma unroll
            for (int j = 0; j < 4; j++)
#pragma unroll
                for (int q = 0; q < 4; q++) sacc[j][q] = 0.f;
            uint32_t aoffq = (uint32_t)((wm * 16 + (lane & 15)) * 80 + ((lane >> 4) << 4));
            uint32_t nloc = (uint32_t)(((lane >> 4) << 3) + (lane & 7));
            uint32_t boffk = (uint32_t)((wn * 32 + nloc) * 80 + (((lane >> 3) & 1) << 4));
#pragma unroll
            for (int s = 0; s < 2; s++) {
                uint32_t ko = (uint32_t)(s * 32);
                uint32_t qh[4], ql[4], kh0[4], kh1[4], kl0[4], kl1[4];
                ldsm4(smu + QA_HI + aoffq + ko, qh);
                ldsm4(smu + QA_LO + aoffq + ko, ql);
                ldsm4(smu + KB_HI + boffk + ko, kh0);
                ldsm4(smu + KB_LO + boffk + ko, kl0);
                mma16816(sacc[0], qh, kh0[0], kh0[1]);
                mma16816(sacc[1], qh, kh0[2], kh0[3]);
                mma16816(sacc[0], qh, kl0[0], kl0[1]);
                mma16816(sacc[1], qh, kl0[2], kl0[3]);
                mma16816(sacc[0], ql, kh0[0], kh0[1]);
                mma16816(sacc[1], ql, kh0[2], kh0[3]);
                if (wn < 2) {   // cols 80-95 are pure padding for wn==2
                    ldsm4(smu + KB_HI + boffk + 1280u + ko, kh1);
                    ldsm4(smu + KB_LO + boffk + 1280u + ko, kl1);
                    mma16816(sacc[2], qh, kh1[0], kh1[1]);
                    mma16816(sacc[3], qh, kh1[2], kh1[3]);
                    mma16816(sacc[2], qh, kl1[0], kl1[1]);
                    mma16816(sacc[3], qh, kl1[2], kl1[3]);
                    mma16816(sacc[2], ql, kh1[0], kh1[1]);
                    mma16816(sacc[3], ql, kh1[2], kh1[3]);
                }
            }
            int r0 = wm * 16 + (lane >> 2);
#pragma unroll
            for (int j = 0; j < 4; j++) {
                int col = wn * 32 + j * 8 + ((lane & 3) << 1);
#pragma unroll
                for (int e = 0; e < 4; e++) {
                    int r = (e < 2) ? r0 : r0 + 8;
                    int c = col + (e & 1);
                    if (r < NT && c < NT) {
                        float s = sacc[j][e];
                        if (r >= 2 && c >= 2) {
                            int i2 = r - 2, j2 = c - 2;
                            int bi = (((i2 >> 3) - (j2 >> 3) + 7) * 15)
                                   + ((i2 & 7) - (j2 & 7) + 7);
                            s += rbt[bi * NH + h];
                        }
                        SSf[r * 68 + c] = s;
                    }
                }
            }
        }
        __syncthreads();

        // ---- softmax: SS -> P fp16 hi/lo; re-zero P pad cols (overlay clobbers) ----
        for (int row = warp; row < NT; row += 16) {
            float* sp = &SSf[row * 68];
            float v0 = sp[lane], v1 = sp[c1];
            float v2 = has2 ? sp[c2] : -INFINITY;
            float mx = fmaxf(fmaxf(v0, v1), v2);
#pragma unroll
            for (int o = 16; o > 0; o >>= 1)
                mx = fmaxf(mx, __shfl_xor_sync(0xffffffffu, mx, o));
            float e0 = __expf(v0 - mx), e1 = __expf(v1 - mx);
            float e2 = has2 ? __expf(v2 - mx) : 0.f;
            float s = e0 + e1 + e2;
#pragma unroll
            for (int o = 16; o > 0; o >>= 1)
                s += __shfl_xor_sync(0xffffffffu, s, o);
            float inv = 1.f / s;
            __half ph, pl;
            hilo1(e0 * inv, ph, pl);
            *(__half*)(smb + PA_HI + row * 176 + lane * 2) = ph;
            *(__half*)(smb + PA_LO + row * 176 + lane * 2) = pl;
            hilo1(e1 * inv, ph, pl);
            *(__half*)(smb + PA_HI + row * 176 + c1 * 2) = ph;
            *(__half*)(smb + PA_LO + row * 176 + c1 * 2) = pl;
            if (has2) {
                hilo1(e2 * inv, ph, pl);
                *(__half*)(smb + PA_HI + row * 176 + c2 * 2) = ph;
                *(__half*)(smb + PA_LO + row * 176 + c2 * 2) = pl;
            }
            if (lane < 11) {   // zero pad cols 66-87 (bytes 132..176)
                *(uint32_t*)(smb + PA_HI + row * 176 + 132 + lane * 4) = 0u;
                *(uint32_t*)(smb + PA_LO + row * 176 + 132 + lane * 4) = 0u;
            }
        }
        __syncthreads();

        // ---- PV MMA (warps 0-4, m16n32): O -> global fp16 hi/lo ----
        if (warp < 5) {
            float pacc[4][4];
#pragma unroll
            for (int j = 0; j < 4; j++)
#pragma unroll
                for (int q = 0; q < 4; q++) pacc[j][q] = 0.f;
            uint32_t aoffp = (uint32_t)((warp * 16 + (lane & 15)) * 176 + ((lane >> 4) << 4));
            uint32_t nloc = (uint32_t)(((lane >> 4) << 3) + (lane & 7));
            uint32_t boffv = (uint32_t)(nloc * 176 + (((lane >> 3) & 1) << 4));
#pragma unroll
            for (int s = 0; s < 5; s++) {
                uint32_t ko = (uint32_t)(s * 32);
                uint32_t ph4[4], pl4[4], vh0[4], vh1[4], vl0[4], vl1[4];
                ldsm4(smu + PA_HI + aoffp + ko, ph4);
                ldsm4(smu + PA_LO + aoffp + ko, pl4);
                ldsm4(smu + VT_HI + boffv + ko, vh0);
                ldsm4(smu + VT_HI + boffv + 2816u + ko, vh1);
                ldsm4(smu + VT_LO + boffv + ko, vl0);
                ldsm4(smu + VT_LO + boffv + 2816u + ko, vl1);
                mma_block(pacc, ph4, vh0, vh1);
                mma_block(pacc, ph4, vl0, vl1);
                mma_block(pacc, pl4, vh0, vh1);
            }
            int r0 = warp * 16 + (lane >> 2), r1 = r0 + 8;
#pragma unroll
            for (int j = 0; j < 4; j++) {
                int c = (h << 5) + j * 8 + ((lane & 3) << 1);
                __half h0, l0, h1, l1;
                if (r0 < NT) {
                    hilo1(pacc[j][0], h0, l0); hilo1(pacc[j][1], h1, l1);
                    size_t gi = ((size_t)b * NT + r0) * 256 + c;
                    *(uint32_t*)&OHI_g[gi] = packh(h0, h1);
                    *(uint32_t*)&OLO_g[gi] = packh(l0, l1);
                }
                if (r1 < NT) {
                    hilo1(pacc[j][2], h0, l0); hilo1(pacc[j][3], h1, l1);
                    size_t gi = ((size_t)b * NT + r1) * 256 + c;
                    *(uint32_t*)&OHI_g[gi] = packh(h0, h1);
                    *(uint32_t*)&OLO_g[gi] = packh(l0, l1);
                }
            }
        }
        __syncthreads();   // PV done before next epilogue overwrites PA(=QA/KB)
    }

    // ---- output projection: A = O from global scratch, N=256 in 3 chunks ----
#pragma unroll 1
    for (int t = 0; t < 3; t++) {
        int nvalid = (t == 2) ? 64 : 96;
        float acc[4][4];
#pragma unroll
        for (int j = 0; j < 4; j++)
#pragma unroll
            for (int q = 0; q < 4; q++) acc[j][q] = 0.f;

        gemm_full(1, xg, b, 1, 0, 96 * t, nvalid, smb, smu, tid, warp, lane, acc);

        if (warp < 15) {
            int r0 = wm * 16 + (lane >> 2), r1 = r0 + 8;
#pragma unroll
            for (int j = 0; j < 4; j++) {
                int col = 96 * t + wn * 32 + j * 8 + ((lane & 3) << 1);
                if (col < 256) {
                    float pb0 = proj_b[col], pb1 = proj_b[col + 1];
                    if (r0 < NT) {
                        float2 v; v.x = acc[j][0] + pb0; v.y = acc[j][1] + pb1;
                        *(float2*)(og + r0 * 256 + col) = v;
                    }
                    if (r1 < NT) {
                        float2 v; v.x = acc[j][2] + pb0; v.y = acc[j][3] + pb1;
                        *(float2*)(og + r1 * 256 + col) = v;
                    }
                }
            }
        }
    }
}

extern "C" void kernel_launch(void* const* d_in, const int* in_sizes, int n_in,
                              void* d_out, int out_size) {
    const float* x      = (const float*)d_in[0];
    const float* qkv_w  = (const float*)d_in[1];
    const float* qkv_b  = (const float*)d_in[2];
    const float* rbt    = (const float*)d_in[3];
    const float* proj_w = (const float*)d_in[4];
    const float* proj_b = (const float*)d_in[5];
    float* out = (float*)d_out;

    precvt_k<<<256, 256>>>(qkv_w, proj_w);

    cudaFuncSetAttribute(winattn_mma,
                         cudaFuncAttributeMaxDynamicSharedMemorySize, SMEM_BYTES);
    winattn_mma<<<NWIN, NTHREADS, SMEM_BYTES>>>(x, qkv_b, rbt, proj_b, out);
}